// round 1
// baseline (speedup 1.0000x reference)
#include <cuda_runtime.h>
#include <math.h>

#define H 1024
#define BB 16384
#define NSTEPS 8
#define NBIG 8192  // [ op1(1024) | num1(1024) | gi r,z,n (3072) | gh r,z,n (3072) ]

#define BM 128
#define BN 64
#define BK 16
#define TM 8
#define TN 4

// ---- scratch (device globals: the sanctioned no-alloc workaround) ----
__device__ float g_W[H * NBIG];                      // 32 MB fused weight matrix
__device__ float g_bias[NBIG];
__device__ float g_Y[(size_t)BB * NBIG];             // 512 MB pre-activations per step

// ---- helpers ----
__device__ __forceinline__ float gelu_f(float x) {
    return 0.5f * x * (1.0f + erff(x * 0.70710678118654752440f));
}
__device__ __forceinline__ float sigmoid_f(float x) {
    return 1.0f / (1.0f + expf(-x));
}
__device__ __forceinline__ unsigned long long pack2(float lo, float hi) {
    unsigned long long r;
    asm("mov.b64 %0, {%1,%2};" : "=l"(r) : "f"(lo), "f"(hi));
    return r;
}
__device__ __forceinline__ void ffma2(unsigned long long& d, unsigned long long a, unsigned long long b) {
    asm("fma.rn.f32x2 %0, %1, %2, %0;" : "+l"(d) : "l"(a), "l"(b));
}
__device__ __forceinline__ float2 unpack2(unsigned long long v) {
    float2 r;
    asm("mov.b64 {%0,%1}, %2;" : "=f"(r.x), "=f"(r.y) : "l"(v));
    return r;
}

// ---- build fused weight matrix W_big[k][n] and bias ----
__global__ void prep_kernel(const float* __restrict__ w_op1, const float* __restrict__ b_op1,
                            const float* __restrict__ w_num1, const float* __restrict__ b_num1,
                            const float* __restrict__ w_ih, const float* __restrict__ b_ih,
                            const float* __restrict__ w_hh, const float* __restrict__ b_hh) {
    int idx = blockIdx.x * blockDim.x + threadIdx.x;
    if (idx >= H * NBIG) return;
    int k = idx / NBIG;
    int n = idx - k * NBIG;
    float v;
    if (n < 1024)       v = w_op1[k * H + n];
    else if (n < 2048)  v = w_num1[k * H + (n - 1024)];
    else if (n < 5120)  v = w_ih[(size_t)(n - 2048) * H + k];   // transpose: gi[m]=sum_k h[k]*w_ih[m][k]
    else                v = w_hh[(size_t)(n - 5120) * H + k];
    g_W[idx] = v;
    if (k == 0) {
        float bb;
        if (n < 1024)       bb = b_op1[n];
        else if (n < 2048)  bb = b_num1[n - 1024];
        else if (n < 5120)  bb = b_ih[n - 2048];
        else                bb = b_hh[n - 5120];
        g_bias[n] = bb;
    }
}

// ---- big fused GEMM: g_Y = h @ g_W + g_bias  (M=16384, N=8192, K=1024) ----
__global__ __launch_bounds__(256) void gemm_kernel(const float* __restrict__ A) {
    __shared__ float As[BK][BM + 4];
    __shared__ float Bs[BK][BN];

    int bm = blockIdx.y, bn = blockIdx.x;
    int tid = threadIdx.x;
    int tx = tid & 15;    // 0..15 -> 4 cols each
    int ty = tid >> 4;    // 0..15 -> 8 rows each

    unsigned long long acc2[TM][TN / 2];
    #pragma unroll
    for (int i = 0; i < TM; i++) { acc2[i][0] = 0ull; acc2[i][1] = 0ull; }

    const float* Ablk = A + (size_t)bm * BM * H;
    const float* Wblk = g_W + (size_t)bn * BN;

    for (int k0 = 0; k0 < H; k0 += BK) {
        // stage A: 128 rows x 16 cols, as float4 (512 float4 / 256 thr = 2 each)
        #pragma unroll
        for (int i = 0; i < 2; i++) {
            int li = tid + i * 256;
            int row = li >> 2;
            int c4 = li & 3;
            float4 v = *(const float4*)(Ablk + (size_t)row * H + k0 + c4 * 4);
            As[c4 * 4 + 0][row] = v.x;
            As[c4 * 4 + 1][row] = v.y;
            As[c4 * 4 + 2][row] = v.z;
            As[c4 * 4 + 3][row] = v.w;
        }
        // stage B: 16 rows x 64 cols (256 float4, 1 each)
        {
            int row = tid >> 4, c4 = tid & 15;
            float4 v = *(const float4*)(Wblk + (size_t)(k0 + row) * NBIG + c4 * 4);
            *(float4*)&Bs[row][c4 * 4] = v;
        }
        __syncthreads();

        #pragma unroll
        for (int k = 0; k < BK; k++) {
            float4 av0 = *(const float4*)&As[k][ty * TM];
            float4 av1 = *(const float4*)&As[k][ty * TM + 4];
            float4 bv  = *(const float4*)&Bs[k][tx * TN];
            unsigned long long b0 = pack2(bv.x, bv.y);
            unsigned long long b1 = pack2(bv.z, bv.w);
            float av[TM] = {av0.x, av0.y, av0.z, av0.w, av1.x, av1.y, av1.z, av1.w};
            #pragma unroll
            for (int i = 0; i < TM; i++) {
                unsigned long long a2 = pack2(av[i], av[i]);
                ffma2(acc2[i][0], a2, b0);
                ffma2(acc2[i][1], a2, b1);
            }
        }
        __syncthreads();
    }

    int n0 = bn * BN + tx * TN;
    float4 bias = *(const float4*)&g_bias[n0];
    #pragma unroll
    for (int i = 0; i < TM; i++) {
        int m = bm * BM + ty * TM + i;
        float2 lo = unpack2(acc2[i][0]);
        float2 hi = unpack2(acc2[i][1]);
        float4 o;
        o.x = lo.x + bias.x;
        o.y = lo.y + bias.y;
        o.z = hi.x + bias.z;
        o.w = hi.y + bias.w;
        *(float4*)(g_Y + (size_t)m * NBIG + n0) = o;
    }
}

// ---- op/num heads: one warp per row, GELU + tiny projections ----
__global__ __launch_bounds__(256) void heads_kernel(
    const float* __restrict__ w_op2, const float* __restrict__ b_op2,
    const float* __restrict__ w_num2, const float* __restrict__ b_num2,
    float* __restrict__ ops, float* __restrict__ nums)
{
    __shared__ float s_w2[H * 5];
    __shared__ float s_wn[H];
    int tid = threadIdx.x;
    for (int i = tid; i < H * 5; i += 256) s_w2[i] = w_op2[i];
    for (int i = tid; i < H; i += 256)     s_wn[i] = w_num2[i];
    __syncthreads();

    int warp = tid >> 5, lane = tid & 31;
    int b = blockIdx.x * 8 + warp;
    const float* Yr = g_Y + (size_t)b * NBIG;

    float a0 = 0.f, a1 = 0.f, a2 = 0.f, a3 = 0.f, a4 = 0.f, an = 0.f;
    for (int j = lane; j < H; j += 32) {
        float g = gelu_f(Yr[j]);
        a0 += g * s_w2[j * 5 + 0];
        a1 += g * s_w2[j * 5 + 1];
        a2 += g * s_w2[j * 5 + 2];
        a3 += g * s_w2[j * 5 + 3];
        a4 += g * s_w2[j * 5 + 4];
        float gn = gelu_f(Yr[H + j]);
        an += gn * s_wn[j];
    }
    #pragma unroll
    for (int off = 16; off > 0; off >>= 1) {
        a0 += __shfl_xor_sync(0xffffffffu, a0, off);
        a1 += __shfl_xor_sync(0xffffffffu, a1, off);
        a2 += __shfl_xor_sync(0xffffffffu, a2, off);
        a3 += __shfl_xor_sync(0xffffffffu, a3, off);
        a4 += __shfl_xor_sync(0xffffffffu, a4, off);
        an += __shfl_xor_sync(0xffffffffu, an, off);
    }
    if (lane == 0) {
        float* o = ops + (size_t)b * 5;
        o[0] = a0 + b_op2[0];
        o[1] = a1 + b_op2[1];
        o[2] = a2 + b_op2[2];
        o[3] = a3 + b_op2[3];
        o[4] = a4 + b_op2[4];
        nums[b] = an + b_num2[0];
    }
}

// ---- GRU elementwise update ----
__global__ void gru_kernel(const float* __restrict__ hin, float* __restrict__ hout) {
    int idx = blockIdx.x * blockDim.x + threadIdx.x;
    int b = idx >> 10;
    int j = idx & 1023;
    const float* Yr = g_Y + (size_t)b * NBIG;
    float ir = Yr[2048 + j];
    float iz = Yr[3072 + j];
    float in_ = Yr[4096 + j];
    float hr = Yr[5120 + j];
    float hz = Yr[6144 + j];
    float hn = Yr[7168 + j];
    float h = hin[idx];
    float r = sigmoid_f(ir + hr);
    float z = sigmoid_f(iz + hz);
    float n = tanhf(in_ + r * hn);
    hout[idx] = (1.0f - z) * n + z * h;
}

extern "C" void kernel_launch(void* const* d_in, const int* in_sizes, int n_in,
                              void* d_out, int out_size) {
    const float* x      = (const float*)d_in[0];
    // d_in[1] = num_steps (always 8)
    const float* w_op1  = (const float*)d_in[2];
    const float* b_op1  = (const float*)d_in[3];
    const float* w_op2  = (const float*)d_in[4];
    const float* b_op2  = (const float*)d_in[5];
    const float* w_num1 = (const float*)d_in[6];
    const float* b_num1 = (const float*)d_in[7];
    const float* w_num2 = (const float*)d_in[8];
    const float* b_num2 = (const float*)d_in[9];
    const float* w_ih   = (const float*)d_in[10];
    const float* b_ih   = (const float*)d_in[11];
    const float* w_hh   = (const float*)d_in[12];
    const float* b_hh   = (const float*)d_in[13];

    float* out = (float*)d_out;
    float* final_state = out;                                  // [B,H]
    float* ops    = out + (size_t)BB * H;                      // [8,B,5]
    float* nums   = ops + (size_t)NSTEPS * BB * 5;             // [8,B,1]
    float* states = nums + (size_t)NSTEPS * BB;                // [8,B,H]

    prep_kernel<<<(H * NBIG + 255) / 256, 256>>>(w_op1, b_op1, w_num1, b_num1,
                                                 w_ih, b_ih, w_hh, b_hh);
    // states[0] = x (state before step 0); state chaining lives inside the output buffer
    cudaMemcpyAsync(states, x, (size_t)BB * H * sizeof(float), cudaMemcpyDeviceToDevice);

    for (int s = 0; s < NSTEPS; s++) {
        const float* h = states + (size_t)s * BB * H;
        float* hnext = (s < NSTEPS - 1) ? states + (size_t)(s + 1) * BB * H : final_state;

        dim3 grid(NBIG / BN, BB / BM);
        gemm_kernel<<<grid, 256>>>(h);
        heads_kernel<<<BB / 8, 256>>>(w_op2, b_op2, w_num2, b_num2,
                                      ops + (size_t)s * BB * 5, nums + (size_t)s * BB);
        gru_kernel<<<(BB * H) / 256, 256>>>(h, hnext);
    }
}

// round 3
// speedup vs baseline: 2.7379x; 2.7379x over previous
#include <cuda_runtime.h>
#include <cuda_bf16.h>
#include <math.h>
#include <stdint.h>

#define H 1024
#define BB 16384
#define NSTEPS 8
#define NBIG 8192  // [ op1(1024) | num1(1024) | gi r,z,n (3072) | gh r,z,n (3072) ]

// GEMM tiling
#define BM 128
#define BN 128
#define BK 32
#define STAGES 3
#define TILE_BYTES 8192            // one operand tile (128 rows x 32 bf16)
#define STAGE_BYTES (4 * TILE_BYTES)
#define GEMM_SMEM (STAGES * STAGE_BYTES)   // 98304

// ---- scratch (device globals: sanctioned no-alloc workaround) ----
__device__ __nv_bfloat16 g_Bhi[(size_t)NBIG * H];   // 16 MB  W_big hi, [n][k]
__device__ __nv_bfloat16 g_Blo[(size_t)NBIG * H];   // 16 MB  W_big lo, [n][k]
__device__ __nv_bfloat16 g_Ahi[(size_t)BB * H];     // 32 MB  h hi
__device__ __nv_bfloat16 g_Alo[(size_t)BB * H];     // 32 MB  h lo
__device__ float g_bias[NBIG];
__device__ float g_Y[(size_t)BB * NBIG];            // 512 MB

// ================= helpers =================
__device__ __forceinline__ uint32_t smem_u32(const void* p) {
    uint32_t a;
    asm("{ .reg .u64 t; cvta.to.shared.u64 t, %1; cvt.u32.u64 %0, t; }" : "=r"(a) : "l"(p));
    return a;
}
__device__ __forceinline__ void cpasync16(uint32_t s, const void* g) {
    asm volatile("cp.async.cg.shared.global [%0], [%1], 16;" :: "r"(s), "l"(g) : "memory");
}
__device__ __forceinline__ void cp_commit() {
    asm volatile("cp.async.commit_group;" ::: "memory");
}
__device__ __forceinline__ void cp_wait1() {
    asm volatile("cp.async.wait_group 1;" ::: "memory");
}
__device__ __forceinline__ void cp_wait0() {
    asm volatile("cp.async.wait_group 0;" ::: "memory");
}
__device__ __forceinline__ void ldsm4(uint32_t a, uint32_t& r0, uint32_t& r1, uint32_t& r2, uint32_t& r3) {
    asm volatile("ldmatrix.sync.aligned.m8n8.x4.shared.b16 {%0,%1,%2,%3}, [%4];"
                 : "=r"(r0), "=r"(r1), "=r"(r2), "=r"(r3) : "r"(a));
}
__device__ __forceinline__ void mma16816(float* c, const uint32_t* a, const uint32_t* b) {
    asm volatile("mma.sync.aligned.m16n8k16.row.col.f32.bf16.bf16.f32 "
                 "{%0,%1,%2,%3}, {%4,%5,%6,%7}, {%8,%9}, {%0,%1,%2,%3};"
                 : "+f"(c[0]), "+f"(c[1]), "+f"(c[2]), "+f"(c[3])
                 : "r"(a[0]), "r"(a[1]), "r"(a[2]), "r"(a[3]), "r"(b[0]), "r"(b[1]));
}
// swizzled byte offset within one 128x32-bf16 tile (64B rows, 4x16B units)
__device__ __forceinline__ uint32_t SW(uint32_t row, uint32_t u) {
    return row * 64u + ((u ^ ((row >> 1) & 3u)) << 4);
}
__device__ __forceinline__ float gelu_f(float x) {
    return 0.5f * x * (1.0f + erff(x * 0.70710678118654752440f));
}
__device__ __forceinline__ float sigmoid_f(float x) {
    return 1.0f / (1.0f + expf(-x));
}

// ================= prep: split weights to bf16 hi/lo in [n][k] layout =================
__global__ void prep_kernel(const float* __restrict__ w_op1, const float* __restrict__ b_op1,
                            const float* __restrict__ w_num1, const float* __restrict__ b_num1,
                            const float* __restrict__ w_ih, const float* __restrict__ b_ih,
                            const float* __restrict__ w_hh, const float* __restrict__ b_hh) {
    int idx = blockIdx.x * blockDim.x + threadIdx.x;
    if (idx >= NBIG * H) return;
    int n = idx >> 10;
    int k = idx & 1023;
    float v;
    if (n < 1024)       v = w_op1[k * H + n];
    else if (n < 2048)  v = w_num1[k * H + (n - 1024)];
    else if (n < 5120)  v = w_ih[(size_t)(n - 2048) * H + k];
    else                v = w_hh[(size_t)(n - 5120) * H + k];
    __nv_bfloat16 hi = __float2bfloat16(v);
    __nv_bfloat16 lo = __float2bfloat16(v - __bfloat162float(hi));
    g_Bhi[idx] = hi;
    g_Blo[idx] = lo;
    if (k == 0) {
        float bb;
        if (n < 1024)       bb = b_op1[n];
        else if (n < 2048)  bb = b_num1[n - 1024];
        else if (n < 5120)  bb = b_ih[n - 2048];
        else                bb = b_hh[n - 5120];
        g_bias[n] = bb;
    }
}

// ================= per-step: split h to bf16 hi/lo =================
__global__ __launch_bounds__(256) void convert_h_kernel(const float* __restrict__ h) {
    int idx = blockIdx.x * blockDim.x + threadIdx.x;   // over BB*H/4
    float4 v = *(const float4*)(h + (size_t)idx * 4);
    __nv_bfloat16 h0 = __float2bfloat16(v.x);
    __nv_bfloat16 h1 = __float2bfloat16(v.y);
    __nv_bfloat16 h2 = __float2bfloat16(v.z);
    __nv_bfloat16 h3 = __float2bfloat16(v.w);
    __nv_bfloat162 p0 = __halves2bfloat162(h0, h1);
    __nv_bfloat162 p1 = __halves2bfloat162(h2, h3);
    *(uint2*)(g_Ahi + (size_t)idx * 4) =
        make_uint2(*(uint32_t*)&p0, *(uint32_t*)&p1);
    __nv_bfloat16 l0 = __float2bfloat16(v.x - __bfloat162float(h0));
    __nv_bfloat16 l1 = __float2bfloat16(v.y - __bfloat162float(h1));
    __nv_bfloat16 l2 = __float2bfloat16(v.z - __bfloat162float(h2));
    __nv_bfloat16 l3 = __float2bfloat16(v.w - __bfloat162float(h3));
    __nv_bfloat162 q0 = __halves2bfloat162(l0, l1);
    __nv_bfloat162 q1 = __halves2bfloat162(l2, l3);
    *(uint2*)(g_Alo + (size_t)idx * 4) =
        make_uint2(*(uint32_t*)&q0, *(uint32_t*)&q1);
}

// ================= mma.sync GEMM: g_Y = h @ W_big + bias =================
__global__ __launch_bounds__(256, 2) void gemm_mma_kernel() {
    extern __shared__ char smem[];
    uint32_t sb = smem_u32(smem);
    int tid = threadIdx.x;
    int lane = tid & 31;
    int wid = tid >> 5;
    int warp_m = wid & 1;     // 2 warps in M -> 64 rows each
    int warp_n = wid >> 1;    // 4 warps in N -> 32 cols each
    int m0 = blockIdx.y * BM;
    int n0 = blockIdx.x * BN;

    // ---- g2s mapping: per array, each thread covers rows (tid>>2) and (tid>>2)+64 at unit tid&3
    int row0 = tid >> 2;
    int u0 = tid & 3;
    uint32_t so0 = SW(row0, u0);
    uint32_t so1 = SW(row0 + 64, u0);
    const __nv_bfloat16* pAhi0 = g_Ahi + (size_t)(m0 + row0) * H + u0 * 8;
    const __nv_bfloat16* pAhi1 = pAhi0 + (size_t)64 * H;
    const __nv_bfloat16* pAlo0 = g_Alo + (size_t)(m0 + row0) * H + u0 * 8;
    const __nv_bfloat16* pAlo1 = pAlo0 + (size_t)64 * H;
    const __nv_bfloat16* pBhi0 = g_Bhi + (size_t)(n0 + row0) * H + u0 * 8;
    const __nv_bfloat16* pBhi1 = pBhi0 + (size_t)64 * H;
    const __nv_bfloat16* pBlo0 = g_Blo + (size_t)(n0 + row0) * H + u0 * 8;
    const __nv_bfloat16* pBlo1 = pBlo0 + (size_t)64 * H;

    // ---- ldmatrix offsets (within a tile) ----
    uint32_t offA[4][2], offB[2][2];
    {
        uint32_t r = (uint32_t)(warp_m * 64 + (lane & 15));
        #pragma unroll
        for (int mi = 0; mi < 4; mi++)
            #pragma unroll
            for (int ks = 0; ks < 2; ks++)
                offA[mi][ks] = SW(r + mi * 16, (uint32_t)(ks * 2 + (lane >> 4)));
        uint32_t rb = (uint32_t)(warp_n * 32 + (lane & 7) + ((lane >> 4) << 3));
        #pragma unroll
        for (int nj2 = 0; nj2 < 2; nj2++)
            #pragma unroll
            for (int ks = 0; ks < 2; ks++)
                offB[nj2][ks] = SW(rb + nj2 * 16, (uint32_t)(ks * 2 + ((lane >> 3) & 1)));
    }

    float acc[4][4][4];
    #pragma unroll
    for (int i = 0; i < 4; i++)
        #pragma unroll
        for (int j = 0; j < 4; j++)
            #pragma unroll
            for (int r = 0; r < 4; r++) acc[i][j][r] = 0.f;

    // ---- pipeline ----
    #define ISSUE(kb, stg) do {                                                    \
        uint32_t base = sb + (stg) * STAGE_BYTES;                                  \
        int ko = (kb) * BK;                                                        \
        cpasync16(base + so0,                    pAhi0 + ko);                      \
        cpasync16(base + so1,                    pAhi1 + ko);                      \
        cpasync16(base + TILE_BYTES + so0,       pAlo0 + ko);                      \
        cpasync16(base + TILE_BYTES + so1,       pAlo1 + ko);                      \
        cpasync16(base + 2 * TILE_BYTES + so0,   pBhi0 + ko);                      \
        cpasync16(base + 2 * TILE_BYTES + so1,   pBhi1 + ko);                      \
        cpasync16(base + 3 * TILE_BYTES + so0,   pBlo0 + ko);                      \
        cpasync16(base + 3 * TILE_BYTES + so1,   pBlo1 + ko);                      \
        cp_commit();                                                               \
    } while (0)

    ISSUE(0, 0);
    ISSUE(1, 1);

    const int NKB = H / BK;   // 32
    for (int kb = 0; kb < NKB; kb++) {
        if (kb < NKB - 2) cp_wait1(); else cp_wait0();
        __syncthreads();

        uint32_t base = sb + (uint32_t)(kb % STAGES) * STAGE_BYTES;
        uint32_t sAhi = base, sAlo = base + TILE_BYTES;
        uint32_t sBhi = base + 2 * TILE_BYTES, sBlo = base + 3 * TILE_BYTES;

        #pragma unroll
        for (int ks = 0; ks < 2; ks++) {
            uint32_t Af[4][4], Bh[4][2], Bl[4][2];
            #pragma unroll
            for (int nj2 = 0; nj2 < 2; nj2++) {
                ldsm4(sBhi + offB[nj2][ks], Bh[nj2 * 2][0], Bh[nj2 * 2][1],
                      Bh[nj2 * 2 + 1][0], Bh[nj2 * 2 + 1][1]);
                ldsm4(sBlo + offB[nj2][ks], Bl[nj2 * 2][0], Bl[nj2 * 2][1],
                      Bl[nj2 * 2 + 1][0], Bl[nj2 * 2 + 1][1]);
            }
            #pragma unroll
            for (int mi = 0; mi < 4; mi++)
                ldsm4(sAhi + offA[mi][ks], Af[mi][0], Af[mi][1], Af[mi][2], Af[mi][3]);
            #pragma unroll
            for (int mi = 0; mi < 4; mi++)
                #pragma unroll
                for (int nj = 0; nj < 4; nj++) {
                    mma16816(acc[mi][nj], Af[mi], Bh[nj]);   // hi*hi
                    mma16816(acc[mi][nj], Af[mi], Bl[nj]);   // hi*lo
                }
            #pragma unroll
            for (int mi = 0; mi < 4; mi++)
                ldsm4(sAlo + offA[mi][ks], Af[mi][0], Af[mi][1], Af[mi][2], Af[mi][3]);
            #pragma unroll
            for (int mi = 0; mi < 4; mi++)
                #pragma unroll
                for (int nj = 0; nj < 4; nj++)
                    mma16816(acc[mi][nj], Af[mi], Bh[nj]);   // lo*hi
        }
        __syncthreads();
        if (kb + 2 < NKB) ISSUE(kb + 2, (kb + 2) % STAGES);
    }

    // ---- epilogue: write Y with bias (direct gmem stores) ----
    #pragma unroll
    for (int nj = 0; nj < 4; nj++) {
        int n = n0 + warp_n * 32 + nj * 8 + (lane & 3) * 2;
        float2 b2 = *(const float2*)&g_bias[n];
        #pragma unroll
        for (int mi = 0; mi < 4; mi++) {
            int m = m0 + warp_m * 64 + mi * 16 + (lane >> 2);
            float2 v0 = make_float2(acc[mi][nj][0] + b2.x, acc[mi][nj][1] + b2.y);
            float2 v1 = make_float2(acc[mi][nj][2] + b2.x, acc[mi][nj][3] + b2.y);
            *(float2*)(g_Y + (size_t)m * NBIG + n) = v0;
            *(float2*)(g_Y + (size_t)(m + 8) * NBIG + n) = v1;
        }
    }
}

// ================= heads =================
__global__ __launch_bounds__(256) void heads_kernel(
    const float* __restrict__ w_op2, const float* __restrict__ b_op2,
    const float* __restrict__ w_num2, const float* __restrict__ b_num2,
    float* __restrict__ ops, float* __restrict__ nums)
{
    __shared__ float s_w2[H * 5];
    __shared__ float s_wn[H];
    int tid = threadIdx.x;
    for (int i = tid; i < H * 5; i += 256) s_w2[i] = w_op2[i];
    for (int i = tid; i < H; i += 256)     s_wn[i] = w_num2[i];
    __syncthreads();

    int warp = tid >> 5, lane = tid & 31;
    int b = blockIdx.x * 8 + warp;
    const float* Yr = g_Y + (size_t)b * NBIG;

    float a0 = 0.f, a1 = 0.f, a2 = 0.f, a3 = 0.f, a4 = 0.f, an = 0.f;
    for (int j = lane; j < H; j += 32) {
        float g = gelu_f(Yr[j]);
        a0 += g * s_w2[j * 5 + 0];
        a1 += g * s_w2[j * 5 + 1];
        a2 += g * s_w2[j * 5 + 2];
        a3 += g * s_w2[j * 5 + 3];
        a4 += g * s_w2[j * 5 + 4];
        float gn = gelu_f(Yr[H + j]);
        an += gn * s_wn[j];
    }
    #pragma unroll
    for (int off = 16; off > 0; off >>= 1) {
        a0 += __shfl_xor_sync(0xffffffffu, a0, off);
        a1 += __shfl_xor_sync(0xffffffffu, a1, off);
        a2 += __shfl_xor_sync(0xffffffffu, a2, off);
        a3 += __shfl_xor_sync(0xffffffffu, a3, off);
        a4 += __shfl_xor_sync(0xffffffffu, a4, off);
        an += __shfl_xor_sync(0xffffffffu, an, off);
    }
    if (lane == 0) {
        float* o = ops + (size_t)b * 5;
        o[0] = a0 + b_op2[0];
        o[1] = a1 + b_op2[1];
        o[2] = a2 + b_op2[2];
        o[3] = a3 + b_op2[3];
        o[4] = a4 + b_op2[4];
        nums[b] = an + b_num2[0];
    }
}

// ================= GRU elementwise =================
__global__ void gru_kernel(const float* __restrict__ hin, float* __restrict__ hout) {
    int idx = blockIdx.x * blockDim.x + threadIdx.x;
    int b = idx >> 10;
    int j = idx & 1023;
    const float* Yr = g_Y + (size_t)b * NBIG;
    float ir = Yr[2048 + j];
    float iz = Yr[3072 + j];
    float in_ = Yr[4096 + j];
    float hr = Yr[5120 + j];
    float hz = Yr[6144 + j];
    float hn = Yr[7168 + j];
    float h = hin[idx];
    float r = sigmoid_f(ir + hr);
    float z = sigmoid_f(iz + hz);
    float n = tanhf(in_ + r * hn);
    hout[idx] = (1.0f - z) * n + z * h;
}

extern "C" void kernel_launch(void* const* d_in, const int* in_sizes, int n_in,
                              void* d_out, int out_size) {
    const float* x      = (const float*)d_in[0];
    const float* w_op1  = (const float*)d_in[2];
    const float* b_op1  = (const float*)d_in[3];
    const float* w_op2  = (const float*)d_in[4];
    const float* b_op2  = (const float*)d_in[5];
    const float* w_num1 = (const float*)d_in[6];
    const float* b_num1 = (const float*)d_in[7];
    const float* w_num2 = (const float*)d_in[8];
    const float* b_num2 = (const float*)d_in[9];
    const float* w_ih   = (const float*)d_in[10];
    const float* b_ih   = (const float*)d_in[11];
    const float* w_hh   = (const float*)d_in[12];
    const float* b_hh   = (const float*)d_in[13];

    float* out = (float*)d_out;
    float* final_state = out;                       // [B,H]
    float* ops    = out + (size_t)BB * H;           // [8,B,5]
    float* nums   = ops + (size_t)NSTEPS * BB * 5;  // [8,B,1]
    float* states = nums + (size_t)NSTEPS * BB;     // [8,B,H]

    cudaFuncSetAttribute(gemm_mma_kernel, cudaFuncAttributeMaxDynamicSharedMemorySize, GEMM_SMEM);

    prep_kernel<<<(NBIG * H + 255) / 256, 256>>>(w_op1, b_op1, w_num1, b_num1,
                                                 w_ih, b_ih, w_hh, b_hh);
    cudaMemcpyAsync(states, x, (size_t)BB * H * sizeof(float), cudaMemcpyDeviceToDevice);

    for (int s = 0; s < NSTEPS; s++) {
        const float* h = states + (size_t)s * BB * H;
        float* hnext = (s < NSTEPS - 1) ? states + (size_t)(s + 1) * BB * H : final_state;

        convert_h_kernel<<<(BB * H / 4) / 256, 256>>>(h);
        dim3 grid(NBIG / BN, BB / BM);
        gemm_mma_kernel<<<grid, 256, GEMM_SMEM>>>();
        heads_kernel<<<BB / 8, 256>>>(w_op2, b_op2, w_num2, b_num2,
                                      ops + (size_t)s * BB * 5, nums + (size_t)s * BB);
        gru_kernel<<<(BB * H) / 256, 256>>>(h, hnext);
    }
}